// round 7
// baseline (speedup 1.0000x reference)
#include <cuda_runtime.h>
#include <cuda_bf16.h>
#include <cstdint>

// Residual quantization, N=65536, D=512, K=1024, L=4.
// Phase 1: bf16 mma.sync (m16n8k16), ldmatrix feed, 3-stage cp.async pipeline,
//          per-thread register candidate tracking on d' = csq - 2*dot.
// Phase 2: exact fp32 rescore of candidates; guaranteed fallback full scan when
//          a thread's 2nd-best is also within margin. First-min-index u64 keys.
// Residual chain exact fp32 via g_res.

#define NROWS 65536
#define DDIM  512
#define KCB   1024
#define LLEV  4
#define ROWS  128
#define TPB   512
#define ASTR  1040
#define MARGIN 0.02f
#define MAXC  16

#define SM_A      0         // 128*1040 = 133120
#define SM_B      133120    // 3*16384 = 49152 -> 182272
#define SM_CSQ    182272    // 4096 -> 186368
#define SM_RSQ    186368    // 512  -> 186880
#define SM_RUNMIN 186880    // 512  -> 187392
#define SM_CCNT   187392    // 512  -> 187904
#define SM_CLIST  187904    // 128*16*4 = 8192 -> 196096 (part aliases first 2KB)
#define SM_ROWKEY 196096    // 1024 -> 197120
#define SM_TOTAL  197120

__device__ float g_csq[LLEV * KCB];
__device__ float g_res[(size_t)NROWS * DDIM];
__device__ __align__(16) __nv_bfloat16 g_cb16[(size_t)LLEV * KCB * DDIM];

__device__ __forceinline__ uint32_t smem_u32(const void* p) {
    uint32_t a;
    asm("{ .reg .u64 t; cvta.to.shared.u64 t, %1; cvt.u32.u64 %0, t; }" : "=r"(a) : "l"(p));
    return a;
}
__device__ __forceinline__ void cpa16(uint32_t dst, const void* src) {
    asm volatile("cp.async.cg.shared.global [%0], [%1], 16;" :: "r"(dst), "l"(src));
}
__device__ __forceinline__ void cpa_commit() {
    asm volatile("cp.async.commit_group;" ::: "memory");
}
__device__ __forceinline__ void ldm_x4(uint32_t addr, uint32_t* r) {
    asm volatile("ldmatrix.sync.aligned.m8n8.x4.shared.b16 {%0,%1,%2,%3}, [%4];"
                 : "=r"(r[0]), "=r"(r[1]), "=r"(r[2]), "=r"(r[3]) : "r"(addr));
}
// order-preserving float<->uint (total order incl. negatives)
__device__ __forceinline__ uint32_t ford(float f) {
    uint32_t u = __float_as_uint(f);
    return u ^ ((uint32_t)((int32_t)u >> 31) | 0x80000000u);
}
__device__ __forceinline__ float ford_inv(uint32_t u) {
    uint32_t v = (u & 0x80000000u) ? (u ^ 0x80000000u) : ~u;
    return __uint_as_float(v);
}

#define MMA16816(c, a0, a1, a2, a3, b0, b1)                                     \
    asm volatile(                                                               \
        "mma.sync.aligned.m16n8k16.row.col.f32.bf16.bf16.f32 "                  \
        "{%0,%1,%2,%3}, {%4,%5,%6,%7}, {%8,%9}, {%0,%1,%2,%3};"                 \
        : "+f"((c)[0]), "+f"((c)[1]), "+f"((c)[2]), "+f"((c)[3])                \
        : "r"(a0), "r"(a1), "r"(a2), "r"(a3), "r"(b0), "r"(b1))

// per-row candidate tracker update
#define UPDK(m, d, code)                                                        \
    if ((d) < b2f[m]) {                                                         \
        if ((d) < bf[m]) { b2f[m] = bf[m]; bf[m] = (d); bc[m] = (code); }       \
        else b2f[m] = (d);                                                      \
    }

__device__ __forceinline__ float dot512(const float* cbrow, int lane,
                                        float4 rv0, float4 rv1, float4 rv2, float4 rv3) {
    const float4* cp = (const float4*)cbrow + lane * 4;
    float4 c0 = cp[0], c1 = cp[1], c2 = cp[2], c3 = cp[3];
    float s = 0.f;
    s = fmaf(rv0.x, c0.x, s); s = fmaf(rv0.y, c0.y, s);
    s = fmaf(rv0.z, c0.z, s); s = fmaf(rv0.w, c0.w, s);
    s = fmaf(rv1.x, c1.x, s); s = fmaf(rv1.y, c1.y, s);
    s = fmaf(rv1.z, c1.z, s); s = fmaf(rv1.w, c1.w, s);
    s = fmaf(rv2.x, c2.x, s); s = fmaf(rv2.y, c2.y, s);
    s = fmaf(rv2.z, c2.z, s); s = fmaf(rv2.w, c2.w, s);
    s = fmaf(rv3.x, c3.x, s); s = fmaf(rv3.y, c3.y, s);
    s = fmaf(rv3.z, c3.z, s); s = fmaf(rv3.w, c3.w, s);
    #pragma unroll
    for (int o = 16; o; o >>= 1) s += __shfl_xor_sync(0xffffffffu, s, o);
    return s;
}

// ---------------------------------------------------------------------------
__global__ void prep_kernel(const float* __restrict__ cb) {
    int warp = (blockIdx.x * blockDim.x + threadIdx.x) >> 5;
    int lane = threadIdx.x & 31;
    if (warp >= LLEV * KCB) return;
    const float4* p = (const float4*)(cb + (size_t)warp * DDIM);
    __nv_bfloat162* o = (__nv_bfloat162*)(g_cb16 + (size_t)warp * DDIM);
    float s = 0.f;
    #pragma unroll
    for (int i = lane; i < DDIM / 4; i += 32) {
        float4 v = p[i];
        s = fmaf(v.x, v.x, s);
        s = fmaf(v.y, v.y, s);
        s = fmaf(v.z, v.z, s);
        s = fmaf(v.w, v.w, s);
        o[2 * i]     = __floats2bfloat162_rn(v.x, v.y);
        o[2 * i + 1] = __floats2bfloat162_rn(v.z, v.w);
    }
    #pragma unroll
    for (int q = 16; q; q >>= 1) s += __shfl_down_sync(0xffffffffu, s, q);
    if (lane == 0) g_csq[warp] = s;
}

// B tile fill: 256 codes x 32 d (64B), XOR-swizzled 16B segments
__device__ __forceinline__ void bload(uint32_t sma, const __nv_bfloat16* cb16l,
                                      int buf, int cq, int dcl, int t) {
    uint32_t dst0 = sma + SM_B + buf * 16384;
    const char* src0 = (const char*)cb16l + (size_t)cq * 256 * 1024 + dcl * 64;
    #pragma unroll
    for (int i = 0; i < 2; ++i) {
        int e = t + i * TPB;            // 0..1023
        int code = e >> 2, seg = e & 3;
        uint32_t off = (uint32_t)(code * 64) + (uint32_t)((seg ^ ((code >> 1) & 3)) << 4);
        cpa16(dst0 + off, src0 + (size_t)code * 1024 + seg * 16);
    }
}

// ---------------------------------------------------------------------------
__global__ void __launch_bounds__(TPB, 1)
rq_kernel(const float* __restrict__ inp, const float* __restrict__ cb,
          float* __restrict__ outq, float* __restrict__ outc, int write_codes)
{
    extern __shared__ char smb[];
    float* csq_s = (float*)(smb + SM_CSQ);
    float* rsq_s = (float*)(smb + SM_RSQ);
    float* part  = (float*)(smb + SM_CLIST);   // aliased: dead before clist is used
    uint32_t* runmin = (uint32_t*)(smb + SM_RUNMIN);
    uint32_t* ccnt   = (uint32_t*)(smb + SM_CCNT);
    int* clist       = (int*)(smb + SM_CLIST);
    unsigned long long* rowkey = (unsigned long long*)(smb + SM_ROWKEY);

    const int t = threadIdx.x, lane = t & 31, wid = t >> 5;
    const int gid = lane >> 2, tig = lane & 3;
    const int wrow = wid & 3, wcol = wid >> 2;      // 4 x 32 rows, 4 x 64 codes
    const int n0 = blockIdx.x * ROWS;
    const uint32_t sma = smem_u32(smb);
    const int l16 = lane & 15, lhi4 = lane >> 4;

    for (int l = 0; l < LLEV; ++l) {
        const float* rptr = (l ? g_res : inp) + (size_t)n0 * DDIM;
        const float* cbl = cb + (size_t)l * KCB * DDIM;
        const __nv_bfloat16* cb16l = g_cb16 + (size_t)l * KCB * DDIM;

        for (int i = t; i < KCB; i += TPB) csq_s[i] = g_csq[l * KCB + i];
        if (t < ROWS) { runmin[t] = 0xFFFFFFFFu; ccnt[t] = 0u; }

        // convert residual -> bf16 A smem; exact rsq partials (R1 128-chunk order)
        {
            int row = t >> 2, seg = t & 3;
            const float4* rp = (const float4*)(rptr + (size_t)row * DDIM + seg * 128);
            char* ap = smb + SM_A + row * ASTR + seg * 256;
            float s = 0.f;
            #pragma unroll
            for (int m = 0; m < 16; ++m) {
                float4 v0 = rp[2 * m], v1 = rp[2 * m + 1];
                s = fmaf(v0.x, v0.x, s); s = fmaf(v0.y, v0.y, s);
                s = fmaf(v0.z, v0.z, s); s = fmaf(v0.w, v0.w, s);
                s = fmaf(v1.x, v1.x, s); s = fmaf(v1.y, v1.y, s);
                s = fmaf(v1.z, v1.z, s); s = fmaf(v1.w, v1.w, s);
                __nv_bfloat162 b0 = __floats2bfloat162_rn(v0.x, v0.y);
                __nv_bfloat162 b1 = __floats2bfloat162_rn(v0.z, v0.w);
                __nv_bfloat162 b2 = __floats2bfloat162_rn(v1.x, v1.y);
                __nv_bfloat162 b3 = __floats2bfloat162_rn(v1.z, v1.w);
                uint4 u;
                u.x = *(uint32_t*)&b0; u.y = *(uint32_t*)&b1;
                u.z = *(uint32_t*)&b2; u.w = *(uint32_t*)&b3;
                *(uint4*)(ap + m * 16) = u;
            }
            part[seg * ROWS + row] = s;
        }
        __syncthreads();
        if (t < ROWS)
            rsq_s[t] = ((part[t] + part[ROWS + t]) + part[2 * ROWS + t]) + part[3 * ROWS + t];

        // ---- phase 1: fused 64-iteration stream (4 cq x 16 dc), 3-stage pipe ----
        float acc[2][8][4];
        #pragma unroll
        for (int i = 0; i < 2; ++i)
            #pragma unroll
            for (int j = 0; j < 8; ++j)
                #pragma unroll
                for (int k = 0; k < 4; ++k) acc[i][j][k] = 0.f;

        float bf[4], b2f[4]; int bc[4];
        #pragma unroll
        for (int m = 0; m < 4; ++m) {
            bf[m] = __int_as_float(0x7f800000);
            b2f[m] = __int_as_float(0x7f800000);
            bc[m] = 0;
        }

        bload(sma, cb16l, 0, 0, 0, t); cpa_commit();
        bload(sma, cb16l, 1, 0, 1, t); cpa_commit();

        const uint32_t aaddr0 = sma + SM_A + (wrow * 32 + l16) * ASTR + (lhi4 << 4);
        for (int it = 0; it < 64; ++it) {
            const int cq = it >> 4, dcl = it & 15;
            asm volatile("cp.async.wait_group 1;" ::: "memory");
            __syncthreads();
            {
                int nit = it + 2;
                if (nit < 64) bload(sma, cb16l, nit % 3, nit >> 4, nit & 15, t);
                cpa_commit();
            }
            const uint32_t bbase = sma + SM_B + (it % 3) * 16384;
            #pragma unroll
            for (int ks = 0; ks < 2; ++ks) {
                uint32_t a0[4], a1[4];
                ldm_x4(aaddr0 + dcl * 64 + ks * 32, a0);
                ldm_x4(aaddr0 + 16 * ASTR + dcl * 64 + ks * 32, a1);
                const int bseg = ks * 2 + lhi4;
                #pragma unroll
                for (int j2 = 0; j2 < 4; ++j2) {
                    int brow = wcol * 64 + j2 * 16 + l16;
                    uint32_t baddr = bbase + brow * 64 + ((bseg ^ ((brow >> 1) & 3)) << 4);
                    uint32_t b[4];
                    ldm_x4(baddr, b);
                    MMA16816(acc[0][2 * j2],     a0[0], a0[1], a0[2], a0[3], b[0], b[2]);
                    MMA16816(acc[0][2 * j2 + 1], a0[0], a0[1], a0[2], a0[3], b[1], b[3]);
                    MMA16816(acc[1][2 * j2],     a1[0], a1[1], a1[2], a1[3], b[0], b[2]);
                    MMA16816(acc[1][2 * j2 + 1], a1[0], a1[1], a1[2], a1[3], b[1], b[3]);
                }
            }
            if (dcl == 15) {
                // per-cq reg epilogue: d' = csq - 2*dot, track best/2nd per row
                const int cqbase = cq * 256;
                #pragma unroll
                for (int i = 0; i < 2; ++i)
                    #pragma unroll
                    for (int j = 0; j < 8; ++j) {
                        int code0 = cqbase + wcol * 64 + j * 8 + tig * 2;
                        float cq0 = csq_s[code0], cq1 = csq_s[code0 + 1];
                        float d0 = fmaf(-2.0f, acc[i][j][0], cq0);
                        float d1 = fmaf(-2.0f, acc[i][j][1], cq1);
                        float d2 = fmaf(-2.0f, acc[i][j][2], cq0);
                        float d3 = fmaf(-2.0f, acc[i][j][3], cq1);
                        UPDK(2 * i,     d0, code0);
                        UPDK(2 * i,     d1, code0 + 1);
                        UPDK(2 * i + 1, d2, code0);
                        UPDK(2 * i + 1, d3, code0 + 1);
                        acc[i][j][0] = 0.f; acc[i][j][1] = 0.f;
                        acc[i][j][2] = 0.f; acc[i][j][3] = 0.f;
                    }
            }
        }

        // ---- level-end: global row minima, candidate append, fallback flag ----
        #pragma unroll
        for (int m = 0; m < 4; ++m) {
            int rowm = wrow * 32 + (m >> 1) * 16 + gid + (m & 1) * 8;
            atomicMin(&runmin[rowm], ford(bf[m]));
        }
        __syncthreads();
        #pragma unroll
        for (int m = 0; m < 4; ++m) {
            int rowm = wrow * 32 + (m >> 1) * 16 + gid + (m & 1) * 8;
            float thr = ford_inv(runmin[rowm]) + MARGIN;
            if (bf[m] < thr) {
                uint32_t sl = atomicAdd(&ccnt[rowm], 1u);
                if (sl < MAXC) clist[rowm * MAXC + sl] = bc[m];
            }
            if (b2f[m] < thr) atomicAdd(&ccnt[rowm], 1000u);  // force full scan
        }
        __syncthreads();

        // ---- phase 2: exact fp32 rescore; overflow/fallback -> full scan ----
        for (int r8 = 0; r8 < 8; ++r8) {
            int row = wid * 8 + r8;
            int cnt = (int)ccnt[row];
            const float4* rp = (const float4*)(rptr + (size_t)row * DDIM) + lane * 4;
            float4 rv0 = rp[0], rv1 = rp[1], rv2 = rp[2], rv3 = rp[3];
            float rsqv = rsq_s[row];
            unsigned long long best = ~0ull;
            if (cnt <= MAXC) {
                for (int q = 0; q < cnt; ++q) {
                    int code = clist[row * MAXC + q];
                    float s = dot512(cbl + (size_t)code * DDIM, lane, rv0, rv1, rv2, rv3);
                    float d = (rsqv + csq_s[code]) - 2.0f * s;
                    unsigned long long key =
                        ((unsigned long long)__float_as_uint(d) << 32) | (unsigned)code;
                    if (key < best) best = key;
                }
            } else {
                for (int code = 0; code < KCB; ++code) {
                    float s = dot512(cbl + (size_t)code * DDIM, lane, rv0, rv1, rv2, rv3);
                    float d = (rsqv + csq_s[code]) - 2.0f * s;
                    unsigned long long key =
                        ((unsigned long long)__float_as_uint(d) << 32) | (unsigned)code;
                    if (key < best) best = key;
                }
            }
            if (lane == 0) rowkey[row] = best;
        }
        __syncthreads();

        // ---- update: quant += e, residual = r - e (exact fp32) ----
        for (int i = t; i < ROWS * (DDIM / 4); i += TPB) {
            int row = i >> 7, dq = i & 127;
            unsigned idx = (unsigned)(rowkey[row] & 0xffffffffu);
            float4 e = ((const float4*)(cbl + (size_t)idx * DDIM))[dq];
            float4* qp = (float4*)(outq + (size_t)(n0 + row) * DDIM) + dq;
            float4 q;
            if (l == 0) q = e;
            else { q = *qp; q.x += e.x; q.y += e.y; q.z += e.z; q.w += e.w; }
            *qp = q;
            if (l < LLEV - 1) {
                float4 v = ((const float4*)(rptr + (size_t)row * DDIM))[dq];
                v.x -= e.x; v.y -= e.y; v.z -= e.z; v.w -= e.w;
                ((float4*)(g_res + (size_t)(n0 + row) * DDIM))[dq] = v;
            }
        }
        if (write_codes && t < ROWS) {
            unsigned idx = (unsigned)(rowkey[t] & 0xffffffffu);
            outc[(size_t)(n0 + t) * LLEV + l] = (float)idx;
        }
        __syncthreads();
    }
}

// ---------------------------------------------------------------------------
extern "C" void kernel_launch(void* const* d_in, const int* in_sizes, int n_in,
                              void* d_out, int out_size) {
    const float* inp = (const float*)d_in[0];
    const float* cb  = (const float*)d_in[1];
    if (n_in >= 2 && in_sizes[0] == LLEV * KCB * DDIM && in_sizes[1] == NROWS * DDIM) {
        const float* tmp = inp; inp = cb; cb = tmp;
    }
    float* outq = (float*)d_out;
    float* outc = nullptr;
    int write_codes = 0;
    long long quant_elems = (long long)NROWS * DDIM;
    if ((long long)out_size >= quant_elems + (long long)NROWS * LLEV) {
        write_codes = 1;
        outc = outq + quant_elems;
    }

    prep_kernel<<<(LLEV * KCB * 32 + 255) / 256, 256>>>(cb);

    cudaFuncSetAttribute(rq_kernel, cudaFuncAttributeMaxDynamicSharedMemorySize, SM_TOTAL);
    rq_kernel<<<NROWS / ROWS, TPB, SM_TOTAL>>>(inp, cb, outq, outc, write_codes);
}

// round 8
// speedup vs baseline: 2.7760x; 2.7760x over previous
#include <cuda_runtime.h>
#include <cuda_fp16.h>
#include <cstdint>

// Residual quantization, N=65536, D=512, K=1024, L=4.
// Phase 1: fp16 mma.sync m16n8k16 (f16 accum), ldmatrix feed, cp.async 2-stage
//          pipeline (1 sync/iter), warp tile 32x128.
// Phase 2: margin-collect (R6-proven) -> exact fp32 rescore; list overflow ->
//          guaranteed full exact scan. First-min-index u64 keys.
// Residual chain exact fp32 via g_res; fp16 mirror g_res16 feeds the MMA.

#define NROWS 65536
#define DDIM  512
#define KCB   1024
#define LLEV  4
#define ROWS  64
#define TPB   256
#define MARGIN 0.02f
#define MAXC  16

#define SM_A      0        // 2*4096   = 8192
#define SM_B      8192     // 2*32768  -> 73728
#define SM_CSQ    73728    // 4096 -> 77824
#define SM_RSQ    77824    // 256  -> 78080
#define SM_RUNMIN 78080    // 256  -> 78336
#define SM_CCNT   78336    // 256  -> 78592
#define SM_CLIST  78592    // 64*16*4 = 4096 -> 82688 (part aliases first 1KB)
#define SM_ROWKEY 82688    // 512 -> 83200
#define SM_TOTAL  83200

__device__ float g_csq[LLEV * KCB];
__device__ float g_res[(size_t)NROWS * DDIM];
__device__ __align__(16) __half g_cb16[(size_t)LLEV * KCB * DDIM];
__device__ __align__(16) __half g_res16[(size_t)NROWS * DDIM];

__device__ __forceinline__ uint32_t smem_u32(const void* p) {
    uint32_t a;
    asm("{ .reg .u64 t; cvta.to.shared.u64 t, %1; cvt.u32.u64 %0, t; }" : "=r"(a) : "l"(p));
    return a;
}
__device__ __forceinline__ void cpa16(uint32_t dst, const void* src) {
    asm volatile("cp.async.cg.shared.global [%0], [%1], 16;" :: "r"(dst), "l"(src));
}
__device__ __forceinline__ void cpa_commit() {
    asm volatile("cp.async.commit_group;" ::: "memory");
}
__device__ __forceinline__ void ldm_x4(uint32_t addr, uint32_t* r) {
    asm volatile("ldmatrix.sync.aligned.m8n8.x4.shared.b16 {%0,%1,%2,%3}, [%4];"
                 : "=r"(r[0]), "=r"(r[1]), "=r"(r[2]), "=r"(r[3]) : "r"(addr));
}

// f16-accum HMMA: D(2 regs f16x2) = A(4) * B(2) + D
#define HMMA(c, a, b0, b1)                                                      \
    asm volatile(                                                               \
        "mma.sync.aligned.m16n8k16.row.col.f16.f16.f16.f16 "                    \
        "{%0,%1}, {%2,%3,%4,%5}, {%6,%7}, {%0,%1};"                             \
        : "+r"((c)[0]), "+r"((c)[1])                                            \
        : "r"((a)[0]), "r"((a)[1]), "r"((a)[2]), "r"((a)[3]), "r"(b0), "r"(b1))

__device__ __forceinline__ float dot512(const float* cbrow, int lane,
                                        float4 rv0, float4 rv1, float4 rv2, float4 rv3) {
    const float4* cp = (const float4*)cbrow + lane * 4;
    float4 c0 = cp[0], c1 = cp[1], c2 = cp[2], c3 = cp[3];
    float s = 0.f;
    s = fmaf(rv0.x, c0.x, s); s = fmaf(rv0.y, c0.y, s);
    s = fmaf(rv0.z, c0.z, s); s = fmaf(rv0.w, c0.w, s);
    s = fmaf(rv1.x, c1.x, s); s = fmaf(rv1.y, c1.y, s);
    s = fmaf(rv1.z, c1.z, s); s = fmaf(rv1.w, c1.w, s);
    s = fmaf(rv2.x, c2.x, s); s = fmaf(rv2.y, c2.y, s);
    s = fmaf(rv2.z, c2.z, s); s = fmaf(rv2.w, c2.w, s);
    s = fmaf(rv3.x, c3.x, s); s = fmaf(rv3.y, c3.y, s);
    s = fmaf(rv3.z, c3.z, s); s = fmaf(rv3.w, c3.w, s);
    #pragma unroll
    for (int o = 16; o; o >>= 1) s += __shfl_xor_sync(0xffffffffu, s, o);
    return s;
}

// ---------------------------------------------------------------------------
__global__ void prep_kernel(const float* __restrict__ cb) {
    int warp = (blockIdx.x * blockDim.x + threadIdx.x) >> 5;
    int lane = threadIdx.x & 31;
    if (warp >= LLEV * KCB) return;
    const float4* p = (const float4*)(cb + (size_t)warp * DDIM);
    __half2* o = (__half2*)(g_cb16 + (size_t)warp * DDIM);
    float s = 0.f;
    #pragma unroll
    for (int i = lane; i < DDIM / 4; i += 32) {
        float4 v = p[i];
        s = fmaf(v.x, v.x, s);
        s = fmaf(v.y, v.y, s);
        s = fmaf(v.z, v.z, s);
        s = fmaf(v.w, v.w, s);
        o[2 * i]     = __float22half2_rn(make_float2(v.x, v.y));
        o[2 * i + 1] = __float22half2_rn(make_float2(v.z, v.w));
    }
    #pragma unroll
    for (int q = 16; q; q >>= 1) s += __shfl_down_sync(0xffffffffu, s, q);
    if (lane == 0) g_csq[warp] = s;
}

__global__ void conv_kernel(const float* __restrict__ inp) {
    size_t i = (size_t)blockIdx.x * blockDim.x + threadIdx.x;  // per float4
    float4 v = ((const float4*)inp)[i];
    __half2 p0 = __float22half2_rn(make_float2(v.x, v.y));
    __half2 p1 = __float22half2_rn(make_float2(v.z, v.w));
    uint2 u;
    u.x = *(uint32_t*)&p0;
    u.y = *(uint32_t*)&p1;
    ((uint2*)g_res16)[i] = u;
}

// ---------------------------------------------------------------------------
// tile fills (XOR-swizzled 16B segments, 64B rows)
// ---------------------------------------------------------------------------
__device__ __forceinline__ void bloadB(uint32_t sma, const __half* cb16l,
                                       int buf, int h, int dcl, int t) {
    uint32_t dst0 = sma + SM_B + buf * 32768;
    const char* src0 = (const char*)cb16l + (size_t)h * 512 * 1024 + dcl * 64;
    #pragma unroll
    for (int i = 0; i < 8; ++i) {
        int e = t + i * TPB;        // 0..2047
        int code = e >> 2, seg = e & 3;
        uint32_t off = (uint32_t)(code * 64) + (uint32_t)((seg ^ ((code >> 1) & 3)) << 4);
        cpa16(dst0 + off, src0 + (size_t)code * 1024 + seg * 16);
    }
}
__device__ __forceinline__ void bloadA(uint32_t sma, const __half* resb,
                                       int buf, int dcl, int t) {
    uint32_t dst0 = sma + SM_A + buf * 4096;
    const char* src0 = (const char*)resb + dcl * 64;
    int row = t >> 2, seg = t & 3;  // 64 rows x 4 segs = 256
    uint32_t off = (uint32_t)(row * 64) + (uint32_t)((seg ^ ((row >> 1) & 3)) << 4);
    cpa16(dst0 + off, src0 + (size_t)row * 1024 + seg * 16);
}

// ---------------------------------------------------------------------------
__global__ void __launch_bounds__(TPB, 2)
rq_kernel(const float* __restrict__ inp, const float* __restrict__ cb,
          float* __restrict__ outq, float* __restrict__ outc, int write_codes)
{
    extern __shared__ char smb[];
    float* csq_s = (float*)(smb + SM_CSQ);
    float* rsq_s = (float*)(smb + SM_RSQ);
    float* part  = (float*)(smb + SM_CLIST);   // alias: dead before clist used
    uint32_t* runmin = (uint32_t*)(smb + SM_RUNMIN);
    uint32_t* ccnt   = (uint32_t*)(smb + SM_CCNT);
    int* clist       = (int*)(smb + SM_CLIST);
    unsigned long long* rowkey = (unsigned long long*)(smb + SM_ROWKEY);

    const int t = threadIdx.x, lane = t & 31, wid = t >> 5;
    const int gid = lane >> 2, tig = lane & 3;
    const int wrow = wid & 1, wcol = wid >> 1;    // 2 x 32 rows, 4 x 128 codes
    const int n0 = blockIdx.x * ROWS;
    const uint32_t sma = smem_u32(smb);
    const int l16 = lane & 15, lhi4 = lane >> 4;
    const __half* resb = g_res16 + (size_t)n0 * DDIM;

    for (int l = 0; l < LLEV; ++l) {
        const float* rptr = (l ? g_res : inp) + (size_t)n0 * DDIM;
        const float* cbl = cb + (size_t)l * KCB * DDIM;
        const __half* cb16l = g_cb16 + (size_t)l * KCB * DDIM;

        for (int i = t; i < KCB; i += TPB) csq_s[i] = g_csq[l * KCB + i];
        if (t < ROWS) { runmin[t] = 0x7f800000u; ccnt[t] = 0u; }

        // prologue fills
        bloadA(sma, resb, 0, 0, t);
        bloadB(sma, cb16l, 0, 0, 0, t);
        cpa_commit();

        // exact fp32 rsq (R1 order: 128-elem chunks then pair-sums)
        {
            int row = t >> 2, seg = t & 3;
            const float4* rp = (const float4*)(rptr + (size_t)row * DDIM + seg * 128);
            float s = 0.f;
            #pragma unroll 8
            for (int i = 0; i < 32; ++i) {
                float4 v = rp[i];
                s = fmaf(v.x, v.x, s); s = fmaf(v.y, v.y, s);
                s = fmaf(v.z, v.z, s); s = fmaf(v.w, v.w, s);
            }
            part[seg * ROWS + row] = s;
        }
        __syncthreads();
        if (t < ROWS)
            rsq_s[t] = ((part[t] + part[ROWS + t]) + part[2 * ROWS + t]) + part[3 * ROWS + t];

        // ---- phase 1: 32 iterations (2 halves x 16 d-chunks), 2-stage pipe ----
        uint32_t acc[2][16][2];
        #pragma unroll
        for (int i = 0; i < 2; ++i)
            #pragma unroll
            for (int j = 0; j < 16; ++j) { acc[i][j][0] = 0u; acc[i][j][1] = 0u; }

        for (int it = 0; it < 32; ++it) {
            const int h = it >> 4, dcl = it & 15, buf = it & 1;
            asm volatile("cp.async.wait_group 0;" ::: "memory");
            __syncthreads();
            {
                int nit = it + 1;
                if (nit < 32) {
                    bloadA(sma, resb, nit & 1, nit & 15, t);
                    bloadB(sma, cb16l, nit & 1, nit >> 4, nit & 15, t);
                }
                cpa_commit();
            }
            const uint32_t abase = sma + SM_A + buf * 4096;
            const uint32_t bbase = sma + SM_B + buf * 32768;
            #pragma unroll
            for (int ks = 0; ks < 2; ++ks) {
                const int kseg = ks * 2 + lhi4;
                uint32_t a0[4], a1[4];
                {
                    int r0 = wrow * 32 + l16;
                    ldm_x4(abase + r0 * 64 + ((kseg ^ ((r0 >> 1) & 3)) << 4), a0);
                    int r1 = r0 + 16;
                    ldm_x4(abase + r1 * 64 + ((kseg ^ ((r1 >> 1) & 3)) << 4), a1);
                }
                #pragma unroll
                for (int j2 = 0; j2 < 8; ++j2) {
                    int code = wcol * 128 + j2 * 16 + l16;
                    uint32_t baddr = bbase + code * 64 + ((kseg ^ ((code >> 1) & 3)) << 4);
                    uint32_t b[4];
                    ldm_x4(baddr, b);
                    HMMA(acc[0][2 * j2],     a0, b[0], b[2]);
                    HMMA(acc[0][2 * j2 + 1], a0, b[1], b[3]);
                    HMMA(acc[1][2 * j2],     a1, b[0], b[2]);
                    HMMA(acc[1][2 * j2 + 1], a1, b[1], b[3]);
                }
            }

            if (dcl == 15) {
                // per-half epilogue: scores, running minima, margin collect
                float smin[4];
                #pragma unroll
                for (int m = 0; m < 4; ++m) smin[m] = __int_as_float(0x7f800000);
                #pragma unroll
                for (int i = 0; i < 2; ++i) {
                    float rq0 = rsq_s[wrow * 32 + i * 16 + gid];
                    float rq1 = rsq_s[wrow * 32 + i * 16 + gid + 8];
                    #pragma unroll
                    for (int j = 0; j < 16; ++j) {
                        int code0 = h * 512 + wcol * 128 + j * 8 + tig * 2;
                        float cq0 = csq_s[code0], cq1 = csq_s[code0 + 1];
                        float2 f0 = __half22float2(*(__half2*)&acc[i][j][0]);
                        float2 f1 = __half22float2(*(__half2*)&acc[i][j][1]);
                        float s0 = (rq0 + cq0) - 2.0f * f0.x;
                        float s1 = (rq0 + cq1) - 2.0f * f0.y;
                        float s2 = (rq1 + cq0) - 2.0f * f1.x;
                        float s3 = (rq1 + cq1) - 2.0f * f1.y;
                        smin[2 * i]     = fminf(smin[2 * i], fminf(s0, s1));
                        smin[2 * i + 1] = fminf(smin[2 * i + 1], fminf(s2, s3));
                    }
                }
                #pragma unroll
                for (int m = 0; m < 4; ++m) {
                    int rowm = wrow * 32 + (m >> 1) * 16 + gid + (m & 1) * 8;
                    atomicMin(&runmin[rowm], __float_as_uint(smin[m]));
                }
                __syncthreads();
                #pragma unroll
                for (int i = 0; i < 2; ++i) {
                    int r0 = wrow * 32 + i * 16 + gid, r1 = r0 + 8;
                    float rq0 = rsq_s[r0], rq1 = rsq_s[r1];
                    float thr0 = __uint_as_float(runmin[r0]) + MARGIN;
                    float thr1 = __uint_as_float(runmin[r1]) + MARGIN;
                    #pragma unroll
                    for (int j = 0; j < 16; ++j) {
                        int code0 = h * 512 + wcol * 128 + j * 8 + tig * 2;
                        float cq0 = csq_s[code0], cq1 = csq_s[code0 + 1];
                        float2 f0 = __half22float2(*(__half2*)&acc[i][j][0]);
                        float2 f1 = __half22float2(*(__half2*)&acc[i][j][1]);
                        float s0 = (rq0 + cq0) - 2.0f * f0.x;
                        float s1 = (rq0 + cq1) - 2.0f * f0.y;
                        float s2 = (rq1 + cq0) - 2.0f * f1.x;
                        float s3 = (rq1 + cq1) - 2.0f * f1.y;
                        if (s0 < thr0) {
                            uint32_t sl = atomicAdd(&ccnt[r0], 1u);
                            if (sl < MAXC) clist[r0 * MAXC + sl] = code0;
                        }
                        if (s1 < thr0) {
                            uint32_t sl = atomicAdd(&ccnt[r0], 1u);
                            if (sl < MAXC) clist[r0 * MAXC + sl] = code0 + 1;
                        }
                        if (s2 < thr1) {
                            uint32_t sl = atomicAdd(&ccnt[r1], 1u);
                            if (sl < MAXC) clist[r1 * MAXC + sl] = code0;
                        }
                        if (s3 < thr1) {
                            uint32_t sl = atomicAdd(&ccnt[r1], 1u);
                            if (sl < MAXC) clist[r1 * MAXC + sl] = code0 + 1;
                        }
                        acc[i][j][0] = 0u; acc[i][j][1] = 0u;
                    }
                }
                __syncthreads();
            }
        }

        // ---- phase 2: exact fp32 rescore; overflow -> full exact scan ----
        for (int r8 = 0; r8 < 8; ++r8) {
            int row = wid * 8 + r8;
            int cnt = (int)ccnt[row];
            const float4* rp = (const float4*)(rptr + (size_t)row * DDIM) + lane * 4;
            float4 rv0 = rp[0], rv1 = rp[1], rv2 = rp[2], rv3 = rp[3];
            float rsqv = rsq_s[row];
            unsigned long long best = ~0ull;
            if (cnt <= MAXC) {
                for (int q = 0; q < cnt; ++q) {
                    int code = clist[row * MAXC + q];
                    float s = dot512(cbl + (size_t)code * DDIM, lane, rv0, rv1, rv2, rv3);
                    float d = (rsqv + csq_s[code]) - 2.0f * s;
                    unsigned long long key =
                        ((unsigned long long)__float_as_uint(d) << 32) | (unsigned)code;
                    if (key < best) best = key;
                }
            } else {
                for (int code = 0; code < KCB; ++code) {
                    float s = dot512(cbl + (size_t)code * DDIM, lane, rv0, rv1, rv2, rv3);
                    float d = (rsqv + csq_s[code]) - 2.0f * s;
                    unsigned long long key =
                        ((unsigned long long)__float_as_uint(d) << 32) | (unsigned)code;
                    if (key < best) best = key;
                }
            }
            if (lane == 0) rowkey[row] = best;
        }
        __syncthreads();

        // ---- update: quant += e, residual = r - e (exact fp32 + fp16 mirror) ----
        for (int i = t; i < ROWS * (DDIM / 4); i += TPB) {
            int row = i >> 7, dq = i & 127;
            unsigned idx = (unsigned)(rowkey[row] & 0xffffffffu);
            float4 e = ((const float4*)(cbl + (size_t)idx * DDIM))[dq];
            float4* qp = (float4*)(outq + (size_t)(n0 + row) * DDIM) + dq;
            float4 q;
            if (l == 0) q = e;
            else { q = *qp; q.x += e.x; q.y += e.y; q.z += e.z; q.w += e.w; }
            *qp = q;
            if (l < LLEV - 1) {
                float4 v = ((const float4*)(rptr + (size_t)row * DDIM))[dq];
                v.x -= e.x; v.y -= e.y; v.z -= e.z; v.w -= e.w;
                ((float4*)(g_res + (size_t)(n0 + row) * DDIM))[dq] = v;
                __half2 p0 = __float22half2_rn(make_float2(v.x, v.y));
                __half2 p1 = __float22half2_rn(make_float2(v.z, v.w));
                uint2 u;
                u.x = *(uint32_t*)&p0;
                u.y = *(uint32_t*)&p1;
                ((uint2*)(g_res16 + (size_t)(n0 + row) * DDIM))[dq] = u;
            }
        }
        if (write_codes && t < ROWS) {
            unsigned idx = (unsigned)(rowkey[t] & 0xffffffffu);
            outc[(size_t)(n0 + t) * LLEV + l] = (float)idx;
        }
        __syncthreads();
    }
}

// ---------------------------------------------------------------------------
extern "C" void kernel_launch(void* const* d_in, const int* in_sizes, int n_in,
                              void* d_out, int out_size) {
    const float* inp = (const float*)d_in[0];
    const float* cb  = (const float*)d_in[1];
    if (n_in >= 2 && in_sizes[0] == LLEV * KCB * DDIM && in_sizes[1] == NROWS * DDIM) {
        const float* tmp = inp; inp = cb; cb = tmp;
    }
    float* outq = (float*)d_out;
    float* outc = nullptr;
    int write_codes = 0;
    long long quant_elems = (long long)NROWS * DDIM;
    if ((long long)out_size >= quant_elems + (long long)NROWS * LLEV) {
        write_codes = 1;
        outc = outq + quant_elems;
    }

    prep_kernel<<<(LLEV * KCB * 32 + 255) / 256, 256>>>(cb);
    conv_kernel<<<(NROWS * (DDIM / 4)) / 256, 256>>>(inp);

    cudaFuncSetAttribute(rq_kernel, cudaFuncAttributeMaxDynamicSharedMemorySize, SM_TOTAL);
    rq_kernel<<<NROWS / ROWS, TPB, SM_TOTAL>>>(inp, cb, outq, outc, write_codes);
}

// round 9
// speedup vs baseline: 2.8539x; 1.0281x over previous
#include <cuda_runtime.h>
#include <cuda_bf16.h>
#include <cstdint>

// Residual quantization, N=65536, D=512, K=1024, L=4.   (R6 base + sched fixes)
// Phase 1: bf16 mma.sync (m16n8k16) approximate scores, ldmatrix operand feed,
//          distance-1 cp.async prefetch into the opposite buffer (1 sync/iter),
//          batched B-fragment loads before each MMA burst.
// Phase 2: margin-filter candidates -> exact fp32 rescore; if a row's candidate
//          count overflows MAXC, full exact scan of all 1024 codes (guaranteed).
// Residual chain exact fp32 via g_res. Codes via first-min-index u64 keys.

#define NROWS 65536
#define DDIM  512
#define KCB   1024
#define LLEV  4
#define ROWS  64
#define TPB   256
#define ASTR  1040        // A row stride bytes (1024 data + 16 pad, conflict-free)
#define MARGIN 0.02f
#define MAXC  16

#define SM_A      0        // 64*1040      = 66560
#define SM_B      66560    // 2*16384      -> 99328 (swizzled, no pad)
#define SM_CSQ    99328    // 4096         -> 103424
#define SM_RSQ    103424   // 256          -> 103680
#define SM_RUNMIN 103680   // 256          -> 103936
#define SM_CCNT   103936   // 256          -> 104192
#define SM_CLIST  104192   // 64*16*4=4096 -> 108288 (PART aliases first 1KB)
#define SM_ROWKEY 108288   // 512          -> 108800
#define SM_TOTAL  108800

__device__ float g_csq[LLEV * KCB];
__device__ float g_res[(size_t)NROWS * DDIM];
__device__ __align__(16) __nv_bfloat16 g_cb16[(size_t)LLEV * KCB * DDIM];

__device__ __forceinline__ uint32_t smem_u32(const void* p) {
    uint32_t a;
    asm("{ .reg .u64 t; cvta.to.shared.u64 t, %1; cvt.u32.u64 %0, t; }" : "=r"(a) : "l"(p));
    return a;
}
__device__ __forceinline__ void cpa16(uint32_t dst, const void* src) {
    asm volatile("cp.async.cg.shared.global [%0], [%1], 16;" :: "r"(dst), "l"(src));
}
__device__ __forceinline__ void cpa_commit() {
    asm volatile("cp.async.commit_group;" ::: "memory");
}
__device__ __forceinline__ void ldm_x4(uint32_t addr, uint32_t* r) {
    asm volatile("ldmatrix.sync.aligned.m8n8.x4.shared.b16 {%0,%1,%2,%3}, [%4];"
                 : "=r"(r[0]), "=r"(r[1]), "=r"(r[2]), "=r"(r[3]) : "r"(addr));
}

#define MMA16816(c, a0, a1, a2, a3, b0, b1)                                     \
    asm volatile(                                                               \
        "mma.sync.aligned.m16n8k16.row.col.f32.bf16.bf16.f32 "                  \
        "{%0,%1,%2,%3}, {%4,%5,%6,%7}, {%8,%9}, {%0,%1,%2,%3};"                 \
        : "+f"((c)[0]), "+f"((c)[1]), "+f"((c)[2]), "+f"((c)[3])                \
        : "r"(a0), "r"(a1), "r"(a2), "r"(a3), "r"(b0), "r"(b1))

__device__ __forceinline__ float dot512(const float* cbrow, int lane,
                                        float4 rv0, float4 rv1, float4 rv2, float4 rv3) {
    const float4* cp = (const float4*)cbrow + lane * 4;
    float4 c0 = cp[0], c1 = cp[1], c2 = cp[2], c3 = cp[3];
    float s = 0.f;
    s = fmaf(rv0.x, c0.x, s); s = fmaf(rv0.y, c0.y, s);
    s = fmaf(rv0.z, c0.z, s); s = fmaf(rv0.w, c0.w, s);
    s = fmaf(rv1.x, c1.x, s); s = fmaf(rv1.y, c1.y, s);
    s = fmaf(rv1.z, c1.z, s); s = fmaf(rv1.w, c1.w, s);
    s = fmaf(rv2.x, c2.x, s); s = fmaf(rv2.y, c2.y, s);
    s = fmaf(rv2.z, c2.z, s); s = fmaf(rv2.w, c2.w, s);
    s = fmaf(rv3.x, c3.x, s); s = fmaf(rv3.y, c3.y, s);
    s = fmaf(rv3.z, c3.z, s); s = fmaf(rv3.w, c3.w, s);
    #pragma unroll
    for (int o = 16; o; o >>= 1) s += __shfl_xor_sync(0xffffffffu, s, o);
    return s;
}

// ---------------------------------------------------------------------------
// prep: exact fp32 csq (R1 order) + bf16-rounded codebook copy
// ---------------------------------------------------------------------------
__global__ void prep_kernel(const float* __restrict__ cb) {
    int warp = (blockIdx.x * blockDim.x + threadIdx.x) >> 5;
    int lane = threadIdx.x & 31;
    if (warp >= LLEV * KCB) return;
    const float4* p = (const float4*)(cb + (size_t)warp * DDIM);
    __nv_bfloat162* o = (__nv_bfloat162*)(g_cb16 + (size_t)warp * DDIM);
    float s = 0.f;
    #pragma unroll
    for (int i = lane; i < DDIM / 4; i += 32) {
        float4 v = p[i];
        s = fmaf(v.x, v.x, s);
        s = fmaf(v.y, v.y, s);
        s = fmaf(v.z, v.z, s);
        s = fmaf(v.w, v.w, s);
        o[2 * i]     = __floats2bfloat162_rn(v.x, v.y);
        o[2 * i + 1] = __floats2bfloat162_rn(v.z, v.w);
    }
    #pragma unroll
    for (int q = 16; q; q >>= 1) s += __shfl_down_sync(0xffffffffu, s, q);
    if (lane == 0) g_csq[warp] = s;
}

// ---------------------------------------------------------------------------
// B tile fill: 256 codes x 32 d (64 bytes), XOR-swizzled 16B segments
// ---------------------------------------------------------------------------
__device__ __forceinline__ void bload(uint32_t sma, const __nv_bfloat16* cb16l,
                                      int buf, int cq, int dc, int t) {
    uint32_t dst0 = sma + SM_B + buf * 16384;
    const char* src0 = (const char*)cb16l + (size_t)cq * 256 * 1024 + dc * 64;
    #pragma unroll
    for (int i = 0; i < 4; ++i) {
        int e = t + i * TPB;            // 0..1023
        int code = e >> 2, seg = e & 3;
        uint32_t off = (uint32_t)(code * 64) + (uint32_t)((seg ^ ((code >> 1) & 3)) << 4);
        cpa16(dst0 + off, src0 + (size_t)code * 1024 + seg * 16);
    }
}

// ---------------------------------------------------------------------------
__global__ void __launch_bounds__(TPB, 2)
rq_kernel(const float* __restrict__ inp, const float* __restrict__ cb,
          float* __restrict__ outq, float* __restrict__ outc, int write_codes)
{
    extern __shared__ char smb[];
    float* csq_s = (float*)(smb + SM_CSQ);
    float* rsq_s = (float*)(smb + SM_RSQ);
    float* part  = (float*)(smb + SM_CLIST);   // aliased: dead before clist is used
    uint32_t* runmin = (uint32_t*)(smb + SM_RUNMIN);
    uint32_t* ccnt   = (uint32_t*)(smb + SM_CCNT);
    int* clist       = (int*)(smb + SM_CLIST);
    unsigned long long* rowkey = (unsigned long long*)(smb + SM_ROWKEY);

    const int t = threadIdx.x, lane = t & 31, wid = t >> 5;
    const int gid = lane >> 2, tig = lane & 3;
    const int wrow = wid & 1, wcol = wid >> 1;
    const int n0 = blockIdx.x * ROWS;
    const uint32_t sma = smem_u32(smb);
    const int l16 = lane & 15, lhi4 = lane >> 4;

    for (int l = 0; l < LLEV; ++l) {
        const float* rptr = (l ? g_res : inp) + (size_t)n0 * DDIM;
        const float* cbl = cb + (size_t)l * KCB * DDIM;
        const __nv_bfloat16* cb16l = g_cb16 + (size_t)l * KCB * DDIM;

        for (int i = t; i < KCB; i += TPB) csq_s[i] = g_csq[l * KCB + i];
        if (t < ROWS) { runmin[t] = 0x7f800000u; ccnt[t] = 0u; }

        // convert residual -> bf16 A smem; exact rsq partials (R1 128-chunk order)
        {
            int row = t >> 2, seg = t & 3;
            const float4* rp = (const float4*)(rptr + (size_t)row * DDIM + seg * 128);
            char* ap = smb + SM_A + row * ASTR + seg * 256;
            float s = 0.f;
            #pragma unroll
            for (int m = 0; m < 16; ++m) {
                float4 v0 = rp[2 * m], v1 = rp[2 * m + 1];
                s = fmaf(v0.x, v0.x, s); s = fmaf(v0.y, v0.y, s);
                s = fmaf(v0.z, v0.z, s); s = fmaf(v0.w, v0.w, s);
                s = fmaf(v1.x, v1.x, s); s = fmaf(v1.y, v1.y, s);
                s = fmaf(v1.z, v1.z, s); s = fmaf(v1.w, v1.w, s);
                __nv_bfloat162 b0 = __floats2bfloat162_rn(v0.x, v0.y);
                __nv_bfloat162 b1 = __floats2bfloat162_rn(v0.z, v0.w);
                __nv_bfloat162 b2 = __floats2bfloat162_rn(v1.x, v1.y);
                __nv_bfloat162 b3 = __floats2bfloat162_rn(v1.z, v1.w);
                uint4 u;
                u.x = *(uint32_t*)&b0; u.y = *(uint32_t*)&b1;
                u.z = *(uint32_t*)&b2; u.w = *(uint32_t*)&b3;
                *(uint4*)(ap + m * 16) = u;
            }
            part[seg * ROWS + row] = s;
        }
        __syncthreads();
        if (t < ROWS)
            rsq_s[t] = ((part[t] + part[ROWS + t]) + part[2 * ROWS + t]) + part[3 * ROWS + t];
        __syncthreads();

        // ---- phase 1: fused 64-iter stream (4 cq x 16 dc), dist-1 prefetch ----
        float acc[2][8][4];
        #pragma unroll
        for (int i = 0; i < 2; ++i)
            #pragma unroll
            for (int j = 0; j < 8; ++j)
                #pragma unroll
                for (int k = 0; k < 4; ++k) acc[i][j][k] = 0.f;

        bload(sma, cb16l, 0, 0, 0, t);
        cpa_commit();

        const uint32_t aaddr0 = sma + SM_A + (wrow * 32 + l16) * ASTR + (lhi4 << 4);
        for (int it = 0; it < 64; ++it) {
            const int cq = it >> 4, dcl = it & 15;
            asm volatile("cp.async.wait_group 0;" ::: "memory");
            __syncthreads();
            // prefetch NEXT tile into the opposite buffer (safe: all warps have
            // finished reading it, since they passed the barrier above after
            // completing iteration it-1's ldmatrix reads)
            {
                int nit = it + 1;
                if (nit < 64) bload(sma, cb16l, nit & 1, nit >> 4, nit & 15, t);
                cpa_commit();
            }
            const uint32_t bbase = sma + SM_B + (it & 1) * 16384;
            #pragma unroll
            for (int ks = 0; ks < 2; ++ks) {
                uint32_t a0[4], a1[4];
                ldm_x4(aaddr0 + dcl * 64 + ks * 32, a0);
                ldm_x4(aaddr0 + 16 * ASTR + dcl * 64 + ks * 32, a1);
                const int bseg = ks * 2 + lhi4;
                // batched B loads, then MMA burst
                uint32_t b[4][4];
                #pragma unroll
                for (int j2 = 0; j2 < 4; ++j2) {
                    int brow = wcol * 64 + j2 * 16 + l16;
                    uint32_t baddr = bbase + brow * 64 + ((bseg ^ ((brow >> 1) & 3)) << 4);
                    ldm_x4(baddr, b[j2]);
                }
                #pragma unroll
                for (int j2 = 0; j2 < 4; ++j2) {
                    MMA16816(acc[0][2 * j2],     a0[0], a0[1], a0[2], a0[3], b[j2][0], b[j2][2]);
                    MMA16816(acc[0][2 * j2 + 1], a0[0], a0[1], a0[2], a0[3], b[j2][1], b[j2][3]);
                    MMA16816(acc[1][2 * j2],     a1[0], a1[1], a1[2], a1[3], b[j2][0], b[j2][2]);
                    MMA16816(acc[1][2 * j2 + 1], a1[0], a1[1], a1[2], a1[3], b[j2][1], b[j2][3]);
                }
            }

            if (dcl == 15) {
                // per-cq epilogue: scores, running minima, margin collect (R6)
                const int cqbase = cq * 256;
                float rsqv[2][2], smin[2][2];
                #pragma unroll
                for (int i = 0; i < 2; ++i)
                    #pragma unroll
                    for (int h = 0; h < 2; ++h) {
                        rsqv[i][h] = rsq_s[wrow * 32 + i * 16 + gid + h * 8];
                        smin[i][h] = __int_as_float(0x7f800000);
                    }
                #pragma unroll
                for (int i = 0; i < 2; ++i)
                    #pragma unroll
                    for (int j = 0; j < 8; ++j) {
                        int code0 = cqbase + wcol * 64 + j * 8 + tig * 2;
                        float cq0 = csq_s[code0], cq1 = csq_s[code0 + 1];
                        float s0 = (rsqv[i][0] + cq0) - 2.0f * acc[i][j][0];
                        float s1 = (rsqv[i][0] + cq1) - 2.0f * acc[i][j][1];
                        float s2 = (rsqv[i][1] + cq0) - 2.0f * acc[i][j][2];
                        float s3 = (rsqv[i][1] + cq1) - 2.0f * acc[i][j][3];
                        acc[i][j][0] = s0; acc[i][j][1] = s1;
                        acc[i][j][2] = s2; acc[i][j][3] = s3;
                        smin[i][0] = fminf(smin[i][0], fminf(s0, s1));
                        smin[i][1] = fminf(smin[i][1], fminf(s2, s3));
                    }
                #pragma unroll
                for (int i = 0; i < 2; ++i)
                    #pragma unroll
                    for (int h = 0; h < 2; ++h)
                        atomicMin(&runmin[wrow * 32 + i * 16 + gid + h * 8],
                                  __float_as_uint(smin[i][h]));
                __syncthreads();
                #pragma unroll
                for (int i = 0; i < 2; ++i) {
                    float thr0 = __uint_as_float(runmin[wrow * 32 + i * 16 + gid]) + MARGIN;
                    float thr1 = __uint_as_float(runmin[wrow * 32 + i * 16 + gid + 8]) + MARGIN;
                    int row0 = wrow * 32 + i * 16 + gid, row1 = row0 + 8;
                    #pragma unroll
                    for (int j = 0; j < 8; ++j) {
                        int code0 = cqbase + wcol * 64 + j * 8 + tig * 2;
                        if (acc[i][j][0] < thr0) {
                            uint32_t sl = atomicAdd(&ccnt[row0], 1u);
                            if (sl < MAXC) clist[row0 * MAXC + sl] = code0;
                        }
                        if (acc[i][j][1] < thr0) {
                            uint32_t sl = atomicAdd(&ccnt[row0], 1u);
                            if (sl < MAXC) clist[row0 * MAXC + sl] = code0 + 1;
                        }
                        if (acc[i][j][2] < thr1) {
                            uint32_t sl = atomicAdd(&ccnt[row1], 1u);
                            if (sl < MAXC) clist[row1 * MAXC + sl] = code0;
                        }
                        if (acc[i][j][3] < thr1) {
                            uint32_t sl = atomicAdd(&ccnt[row1], 1u);
                            if (sl < MAXC) clist[row1 * MAXC + sl] = code0 + 1;
                        }
                        acc[i][j][0] = 0.f; acc[i][j][1] = 0.f;
                        acc[i][j][2] = 0.f; acc[i][j][3] = 0.f;
                    }
                }
                // (next iteration's top barrier orders clist/ccnt before reuse)
            }
        }
        __syncthreads();

        // ---- phase 2: exact fp32 rescore; overflow -> full exact scan ----
        for (int r8 = 0; r8 < 8; ++r8) {
            int row = wid * 8 + r8;
            int cnt = (int)ccnt[row];
            const float4* rp = (const float4*)(rptr + (size_t)row * DDIM) + lane * 4;
            float4 rv0 = rp[0], rv1 = rp[1], rv2 = rp[2], rv3 = rp[3];
            float rsqv = rsq_s[row];
            unsigned long long best = ~0ull;
            if (cnt <= MAXC) {
                for (int q = 0; q < cnt; ++q) {
                    int code = clist[row * MAXC + q];
                    float s = dot512(cbl + (size_t)code * DDIM, lane, rv0, rv1, rv2, rv3);
                    float d = (rsqv + csq_s[code]) - 2.0f * s;
                    unsigned long long key =
                        ((unsigned long long)__float_as_uint(d) << 32) | (unsigned)code;
                    if (key < best) best = key;
                }
            } else {
                // guaranteed-correct slow path: scan all codes exactly
                for (int code = 0; code < KCB; ++code) {
                    float s = dot512(cbl + (size_t)code * DDIM, lane, rv0, rv1, rv2, rv3);
                    float d = (rsqv + csq_s[code]) - 2.0f * s;
                    unsigned long long key =
                        ((unsigned long long)__float_as_uint(d) << 32) | (unsigned)code;
                    if (key < best) best = key;
                }
            }
            if (lane == 0) rowkey[row] = best;
        }
        __syncthreads();

        // ---- update: quant += e, residual = r - e (exact fp32) ----
        for (int i = t; i < ROWS * (DDIM / 4); i += TPB) {
            int row = i >> 7, dq = i & 127;
            unsigned idx = (unsigned)(rowkey[row] & 0xffffffffu);
            float4 e = ((const float4*)(cbl + (size_t)idx * DDIM))[dq];
            float4* qp = (float4*)(outq + (size_t)(n0 + row) * DDIM) + dq;
            float4 q;
            if (l == 0) q = e;
            else { q = *qp; q.x += e.x; q.y += e.y; q.z += e.z; q.w += e.w; }
            *qp = q;
            if (l < LLEV - 1) {
                float4 v = ((const float4*)(rptr + (size_t)row * DDIM))[dq];
                v.x -= e.x; v.y -= e.y; v.z -= e.z; v.w -= e.w;
                ((float4*)(g_res + (size_t)(n0 + row) * DDIM))[dq] = v;
            }
        }
        if (write_codes && t < ROWS) {
            unsigned idx = (unsigned)(rowkey[t] & 0xffffffffu);
            outc[(size_t)(n0 + t) * LLEV + l] = (float)idx;
        }
        __syncthreads();
    }
}

// ---------------------------------------------------------------------------
extern "C" void kernel_launch(void* const* d_in, const int* in_sizes, int n_in,
                              void* d_out, int out_size) {
    const float* inp = (const float*)d_in[0];
    const float* cb  = (const float*)d_in[1];
    if (n_in >= 2 && in_sizes[0] == LLEV * KCB * DDIM && in_sizes[1] == NROWS * DDIM) {
        const float* tmp = inp; inp = cb; cb = tmp;
    }
    float* outq = (float*)d_out;
    float* outc = nullptr;
    int write_codes = 0;
    long long quant_elems = (long long)NROWS * DDIM;
    if ((long long)out_size >= quant_elems + (long long)NROWS * LLEV) {
        write_codes = 1;
        outc = outq + quant_elems;
    }

    prep_kernel<<<(LLEV * KCB * 32 + 255) / 256, 256>>>(cb);

    cudaFuncSetAttribute(rq_kernel, cudaFuncAttributeMaxDynamicSharedMemorySize, SM_TOTAL);
    rq_kernel<<<NROWS / ROWS, TPB, SM_TOTAL>>>(inp, cb, outq, outc, write_codes);
}